// round 7
// baseline (speedup 1.0000x reference)
#include <cuda_runtime.h>
#include <cuda_fp16.h>
#include <cuda_fp8.h>
#include <math.h>

// StateNeuronSep: Luenberger observer, ORDER=4096, SEQ=4096, IN=8, OUT=1.
//
// y_t = r_t.h0 + sum_{k<t} [ (r_k B').u_{t-1-k} + (r_k L) yobs_{t-1-k} ] + D.u_t
// r_{k+1} = r_k A - (r_k.L) C   (row Krylov, rank-1 fold; M never materialized)
// rho(M) ~ 0.9 => truncate at K=144. Precision ladder on A:
//   k in [0,8)    fp32 A      (64 MB/step)
//   k in [8,64)   fp16 copy   (32 MB/step)
//   k in [64,144) fp8 e4m3 copy, scaled 2^14  (16 MB/step)
// Last-finishing CTA per step (atomic counter, fixed sum order => deterministic)
// assembles partial planes, computes s = r.L, applies the fold, writes g_Rfull.

#define Nn 4096
#define Tt 4096
#define INW 8
#define K_TR 144
#define K_F32 8
#define FP8_START 64
#define QP 4
#define FP8_SCALE_INV 6.103515625e-05f   // 2^-14

// Scratch (device globals; no allocation allowed)
__device__ float   g_Rfull[K_TR][Nn];            // assembled Krylov rows, 2.25 MB
__device__ float   g_P[QP][Nn];                  // partial planes (reused each step)
__device__ float   g_PQ[K_TR][12];               // p[0..7], [8]=s_k, [9]=r_k.1
__device__ __half2 g_Ah[(Nn * Nn) / 2];          // 32 MB fp16 A
__device__ unsigned long long g_A8[(Nn * Nn) / 8];  // 16 MB fp8 (e4m3, x2^14) A
__device__ unsigned int g_ctr[K_TR];             // per-step completion counters

// ---------------------------------------------------------------------------
// one-time A (fp32) -> fp16 + scaled fp8.  4M float4 elements.
__global__ void __launch_bounds__(256) convert_kernel(const float4* __restrict__ A4) {
    int idx = blockIdx.x * 256 + threadIdx.x;      // 0 .. 4M-1
    float4 v = A4[idx];
    // fp16
    __half2 h0 = __floats2half2_rn(v.x, v.y);
    __half2 h1 = __floats2half2_rn(v.z, v.w);
    uint2 packed;
    packed.x = *reinterpret_cast<unsigned int*>(&h0);
    packed.y = *reinterpret_cast<unsigned int*>(&h1);
    ((uint2*)g_Ah)[idx] = packed;
    // fp8 e4m3, scaled by 2^14 (max |A|*2^14 ~ 399 < 448)
    const float sc = 16384.f;
    unsigned int b0 = __nv_cvt_float_to_fp8(v.x * sc, __NV_SATFINITE, __NV_E4M3);
    unsigned int b1 = __nv_cvt_float_to_fp8(v.y * sc, __NV_SATFINITE, __NV_E4M3);
    unsigned int b2 = __nv_cvt_float_to_fp8(v.z * sc, __NV_SATFINITE, __NV_E4M3);
    unsigned int b3 = __nv_cvt_float_to_fp8(v.w * sc, __NV_SATFINITE, __NV_E4M3);
    ((unsigned int*)g_A8)[idx] = b0 | (b1 << 8) | (b2 << 16) | (b3 << 24);
}

// ---------------------------------------------------------------------------
// init: r_0 = C, zero the step counters.
__global__ void init_kernel(const float* __restrict__ C) {
    int j = blockIdx.x * 256 + threadIdx.x;
    if (j < Nn) g_Rfull[0][j] = C[j];
    if (blockIdx.x == 0 && threadIdx.x < K_TR) g_ctr[threadIdx.x] = 0;
}

// ---------------------------------------------------------------------------
// Tail work: executed by the LAST CTA of a step (all 512 threads).
// Sums the QP partial planes, computes s = r_k.L (fixed order), folds -s*C,
// writes the assembled r_{k+1}. Deterministic regardless of which CTA runs it.
__device__ __forceinline__ void tail_assemble(int k, const float* r_s,
                                              const float* __restrict__ L,
                                              const float* __restrict__ C,
                                              float* red_s, float* s_bcast) {
    int tid  = threadIdx.x;
    int lane = tid & 31;
    int w    = tid >> 5;

    __threadfence();   // acquire: make other CTAs' partial-plane writes visible

    // s = r_k . L (r_s already staged in smem by the prologue)
    float sp = 0.f;
    #pragma unroll
    for (int it = 0; it < Nn / 512; it++) {
        int i = tid + it * 512;
        sp += r_s[i] * L[i];
    }
    #pragma unroll
    for (int off = 16; off > 0; off >>= 1)
        sp += __shfl_xor_sync(0xffffffffu, sp, off);
    if (lane == 0) red_s[w] = sp;
    __syncthreads();
    if (tid == 0) {
        float s = 0.f;
        #pragma unroll
        for (int q = 0; q < 16; q++) s += red_s[q];
        *s_bcast = s;
    }
    __syncthreads();
    float s = *s_bcast;

    #pragma unroll
    for (int it = 0; it < Nn / 512; it++) {
        int j = tid + it * 512;
        float t = g_P[0][j] + g_P[1][j] + g_P[2][j] + g_P[3][j] - s * C[j];
        g_Rfull[k + 1][j] = t;
    }
}

// Completion protocol shared by all step kernels.
#define STEP_FINISH(k, total)                                                  \
    __syncthreads();                                                           \
    if (tid == 0) {                                                            \
        __threadfence();                                                       \
        unsigned int old = atomicAdd(&g_ctr[k], 1u);                           \
        last_sh = (old == (total) - 1u) ? 1u : 0u;                             \
    }                                                                          \
    __syncthreads();                                                           \
    if (last_sh) tail_assemble(k, r_s, L, C, red_s, &s_sh);

// ---------------------------------------------------------------------------
// fp32 step: grid (64 col-tiles of 64, 4 row-quarters), block 512 (16 warps).
__global__ void __launch_bounds__(512) step32_kernel(int k,
                                                     const float* __restrict__ A,
                                                     const float* __restrict__ C,
                                                     const float* __restrict__ L) {
    __shared__ __align__(16) float r_s[Nn];   // 16 KB
    __shared__ float acc_s[16][64];
    __shared__ float red_s[16];
    __shared__ float s_sh;
    __shared__ unsigned int last_sh;

    int tid  = threadIdx.x;
    int lane = tid & 31;
    int w    = tid >> 5;

    {   // stage assembled r_k
        const float4* rsrc = (const float4*)g_Rfull[k];
        float4* r4 = (float4*)r_s;
        r4[tid]       = rsrc[tid];
        r4[tid + 512] = rsrc[tid + 512];
    }
    __syncthreads();

    int colbase = blockIdx.x * 64;
    size_t c2   = (size_t)(colbase >> 1) + lane;
    int ibase   = blockIdx.y * 1024 + w * 64;

    const unsigned long long* Au = (const unsigned long long*)A;
    unsigned long long acc0 = 0ull, acc1 = 0ull;

    #pragma unroll 4
    for (int ii = 0; ii < 64; ii += 2) {
        int i0 = ibase + ii;
        float r0 = r_s[i0];
        float r1 = r_s[i0 + 1];
        unsigned long long a0 = Au[(size_t)i0 * (Nn / 2) + c2];
        unsigned long long a1 = Au[(size_t)(i0 + 1) * (Nn / 2) + c2];
        unsigned long long rr0, rr1;
        asm("mov.b64 %0, {%1, %1};" : "=l"(rr0) : "r"(__float_as_uint(r0)));
        asm("mov.b64 %0, {%1, %1};" : "=l"(rr1) : "r"(__float_as_uint(r1)));
        asm("fma.rn.f32x2 %0, %1, %2, %3;" : "=l"(acc0) : "l"(a0), "l"(rr0), "l"(acc0));
        asm("fma.rn.f32x2 %0, %1, %2, %3;" : "=l"(acc1) : "l"(a1), "l"(rr1), "l"(acc1));
    }
    unsigned long long accm;
    asm("add.rn.f32x2 %0, %1, %2;" : "=l"(accm) : "l"(acc0), "l"(acc1));
    unsigned int lo_u, hi_u;
    asm("mov.b64 {%0, %1}, %2;" : "=r"(lo_u), "=r"(hi_u) : "l"(accm));
    acc_s[w][lane * 2]     = __uint_as_float(lo_u);
    acc_s[w][lane * 2 + 1] = __uint_as_float(hi_u);
    __syncthreads();

    if (tid < 64) {
        float t = 0.f;
        #pragma unroll
        for (int q = 0; q < 16; q++) t += acc_s[q][tid];
        g_P[blockIdx.y][colbase + tid] = t;
    }

    STEP_FINISH(k, 256u)
}

// ---------------------------------------------------------------------------
// fp16 step: grid (32 col-tiles of 128, 4 row-quarters), block 512.
__global__ void __launch_bounds__(512) step16_kernel(int k,
                                                     const float* __restrict__ C,
                                                     const float* __restrict__ L) {
    __shared__ __align__(16) float r_s[Nn];
    __shared__ float acc_s[16][128];
    __shared__ float red_s[16];
    __shared__ float s_sh;
    __shared__ unsigned int last_sh;

    int tid  = threadIdx.x;
    int lane = tid & 31;
    int w    = tid >> 5;

    {
        const float4* rsrc = (const float4*)g_Rfull[k];
        float4* r4 = (float4*)r_s;
        r4[tid]       = rsrc[tid];
        r4[tid + 512] = rsrc[tid + 512];
    }
    __syncthreads();

    int colbase = blockIdx.x * 128;
    size_t c4   = (size_t)(colbase >> 2) + lane;   // u64 = 4 halves
    int ibase   = blockIdx.y * 1024 + w * 64;

    const unsigned long long* Au = (const unsigned long long*)g_Ah;
    float a0 = 0.f, a1 = 0.f, a2 = 0.f, a3 = 0.f;

    #pragma unroll 4
    for (int ii = 0; ii < 64; ii++) {
        int i = ibase + ii;
        float rv = r_s[i];
        unsigned long long av = Au[(size_t)i * (Nn / 4) + c4];
        unsigned int lo = (unsigned int)av;
        unsigned int hi = (unsigned int)(av >> 32);
        float2 f0 = __half22float2(*(__half2*)&lo);
        float2 f1 = __half22float2(*(__half2*)&hi);
        a0 += rv * f0.x; a1 += rv * f0.y;
        a2 += rv * f1.x; a3 += rv * f1.y;
    }
    acc_s[w][lane * 4]     = a0;
    acc_s[w][lane * 4 + 1] = a1;
    acc_s[w][lane * 4 + 2] = a2;
    acc_s[w][lane * 4 + 3] = a3;
    __syncthreads();

    if (tid < 128) {
        float t = 0.f;
        #pragma unroll
        for (int q = 0; q < 16; q++) t += acc_s[q][tid];
        g_P[blockIdx.y][colbase + tid] = t;
    }

    STEP_FINISH(k, 128u)
}

// ---------------------------------------------------------------------------
// fp8 step: grid (32 col-tiles of 128, 4 row-quarters), block 512.
// Lane covers 8 cols (u64 = 8 e4m3); half-warps handle row pairs.
__global__ void __launch_bounds__(512) step8_kernel(int k,
                                                    const float* __restrict__ C,
                                                    const float* __restrict__ L) {
    __shared__ __align__(16) float r_s[Nn];
    __shared__ float acc_s[16][128];
    __shared__ float red_s[16];
    __shared__ float s_sh;
    __shared__ unsigned int last_sh;

    int tid  = threadIdx.x;
    int lane = tid & 31;
    int w    = tid >> 5;

    {
        const float4* rsrc = (const float4*)g_Rfull[k];
        float4* r4 = (float4*)r_s;
        r4[tid]       = rsrc[tid];
        r4[tid + 512] = rsrc[tid + 512];
    }
    __syncthreads();

    int colbase = blockIdx.x * 128;
    int ibase   = blockIdx.y * 1024 + w * 64;
    int half    = lane >> 4;                       // 0/1: row parity
    int lpos    = lane & 15;                       // col-group within tile
    size_t cu   = (size_t)(colbase >> 3) + lpos;   // u64 index within a row

    const unsigned long long* Au = g_A8;           // row = Nn/8 = 512 u64
    float acc[8];
    #pragma unroll
    for (int c = 0; c < 8; c++) acc[c] = 0.f;

    #pragma unroll 4
    for (int ii = 0; ii < 64; ii += 2) {
        int i = ibase + ii + half;
        float rv = r_s[i];
        unsigned long long av = Au[(size_t)i * (Nn / 8) + cu];
        unsigned short p0 = (unsigned short)av;
        unsigned short p1 = (unsigned short)(av >> 16);
        unsigned short p2 = (unsigned short)(av >> 32);
        unsigned short p3 = (unsigned short)(av >> 48);
        unsigned int h01, h23, h45, h67;
        asm("cvt.rn.f16x2.e4m3x2 %0, %1;" : "=r"(h01) : "h"(p0));
        asm("cvt.rn.f16x2.e4m3x2 %0, %1;" : "=r"(h23) : "h"(p1));
        asm("cvt.rn.f16x2.e4m3x2 %0, %1;" : "=r"(h45) : "h"(p2));
        asm("cvt.rn.f16x2.e4m3x2 %0, %1;" : "=r"(h67) : "h"(p3));
        float2 f0 = __half22float2(*(__half2*)&h01);
        float2 f1 = __half22float2(*(__half2*)&h23);
        float2 f2 = __half22float2(*(__half2*)&h45);
        float2 f3 = __half22float2(*(__half2*)&h67);
        acc[0] += rv * f0.x; acc[1] += rv * f0.y;
        acc[2] += rv * f1.x; acc[3] += rv * f1.y;
        acc[4] += rv * f2.x; acc[5] += rv * f2.y;
        acc[6] += rv * f3.x; acc[7] += rv * f3.y;
    }

    // fold the two row-parity half-warps (lanes 0..15 keep the sum)
    #pragma unroll
    for (int c = 0; c < 8; c++)
        acc[c] += __shfl_down_sync(0xffffffffu, acc[c], 16);
    if (lane < 16) {
        #pragma unroll
        for (int c = 0; c < 8; c++)
            acc_s[w][lpos * 8 + c] = acc[c];
    }
    __syncthreads();

    if (tid < 128) {
        float t = 0.f;
        #pragma unroll
        for (int q = 0; q < 16; q++) t += acc_s[q][tid];
        g_P[blockIdx.y][colbase + tid] = t * FP8_SCALE_INV;
    }

    STEP_FINISH(k, 128u)
}

// ---------------------------------------------------------------------------
// phi: p_k = r_k B - s_k D, q_k = s_k = r_k.L, a_k = r_k.1
__global__ void __launch_bounds__(256) phi_kernel(const float* __restrict__ B,
                                                  const float* __restrict__ D,
                                                  const float* __restrict__ L) {
    __shared__ float r_s[Nn];
    __shared__ float red[256];
    __shared__ float sres[10];
    int k = blockIdx.x;
    int tid = threadIdx.x;

    for (int i = tid; i < Nn; i += 256)
        r_s[i] = g_Rfull[k][i];
    __syncthreads();

    float acc[10];
    #pragma unroll
    for (int c = 0; c < 10; c++) acc[c] = 0.f;

    for (int i = tid; i < Nn; i += 256) {
        float rv = r_s[i];
        float4 b0 = *(const float4*)(B + i * INW);
        float4 b1 = *(const float4*)(B + i * INW + 4);
        acc[0] += rv * b0.x; acc[1] += rv * b0.y;
        acc[2] += rv * b0.z; acc[3] += rv * b0.w;
        acc[4] += rv * b1.x; acc[5] += rv * b1.y;
        acc[6] += rv * b1.z; acc[7] += rv * b1.w;
        acc[8] += rv * L[i];
        acc[9] += rv;                 // h0 = ones
    }

    #pragma unroll
    for (int c = 0; c < 10; c++) {
        red[tid] = acc[c];
        __syncthreads();
        for (int off = 128; off > 0; off >>= 1) {
            if (tid < off) red[tid] += red[tid + off];
            __syncthreads();
        }
        if (tid == 0) sres[c] = red[0];
        __syncthreads();
    }

    if (tid == 0) {
        float s = sres[8];
        #pragma unroll
        for (int c = 0; c < INW; c++) g_PQ[k][c] = sres[c] - s * D[c];
        g_PQ[k][8] = s;
        g_PQ[k][9] = sres[9];
    }
}

// ---------------------------------------------------------------------------
// conv: y_t = a_t + D.u_t + sum_{k<min(t,K)} [ p_k.u_{t-1-k} + q_k yobs_{t-1-k} ]
__global__ void __launch_bounds__(256) conv_kernel(const float* __restrict__ u,
                                                   const float* __restrict__ yobs,
                                                   const float* __restrict__ D,
                                                   float* __restrict__ out) {
    __shared__ float pq[K_TR][10];
    __shared__ float us[512][9];      // [local sidx][0..7]=u, [8]=yobs
    int tid = threadIdx.x;
    int t0  = blockIdx.x * 256;

    for (int idx = tid; idx < K_TR * 10; idx += 256)
        pq[idx / 10][idx % 10] = g_PQ[idx / 10][idx % 10];

    for (int l = tid; l < 512; l += 256) {
        int sidx = t0 - 256 + l;
        if (sidx >= 0 && sidx < Tt) {
            #pragma unroll
            for (int c = 0; c < INW; c++) us[l][c] = u[c * Tt + sidx];
            us[l][8] = yobs[sidx];
        } else {
            #pragma unroll
            for (int c = 0; c < 9; c++) us[l][c] = 0.f;
        }
    }
    __syncthreads();

    int t = t0 + tid;
    float y = 0.f;
    #pragma unroll
    for (int c = 0; c < INW; c++) y += D[c] * u[c * Tt + t];
    if (t < K_TR) y += pq[t][9];      // a_t = r_t . h0 (decayed ~0 beyond K)

    int kmax = min(t, K_TR);
    for (int kk = 0; kk < kmax; kk++) {
        int l = tid + 255 - kk;       // (t-1-kk) - (t0-256)
        float a = pq[kk][8] * us[l][8];
        #pragma unroll
        for (int c = 0; c < INW; c++) a += pq[kk][c] * us[l][c];
        y += a;
    }
    out[t] = 3.f * tanhf(y);
}

// ---------------------------------------------------------------------------
extern "C" void kernel_launch(void* const* d_in, const int* in_sizes, int n_in,
                              void* d_out, int out_size) {
    const float* u    = (const float*)d_in[0];  // [8,4096]
    const float* yobs = (const float*)d_in[1];  // [1,4096]
    const float* A    = (const float*)d_in[2];  // [4096,4096]
    const float* B    = (const float*)d_in[3];  // [4096,8]
    const float* C    = (const float*)d_in[4];  // [1,4096]
    const float* D    = (const float*)d_in[5];  // [1,8]
    const float* L    = (const float*)d_in[6];  // [4096,1]
    float* out = (float*)d_out;                 // [1,4096]
    (void)in_sizes; (void)n_in; (void)out_size;

    convert_kernel<<<(Nn * Nn / 4) / 256, 256>>>((const float4*)A);
    init_kernel<<<Nn / 256, 256>>>(C);
    for (int k = 0; k < K_F32; k++)
        step32_kernel<<<dim3(64, QP), 512>>>(k, A, C, L);
    for (int k = K_F32; k < FP8_START; k++)
        step16_kernel<<<dim3(32, QP), 512>>>(k, C, L);
    for (int k = FP8_START; k < K_TR - 1; k++)
        step8_kernel<<<dim3(32, QP), 512>>>(k, C, L);
    phi_kernel<<<K_TR, 256>>>(B, D, L);
    conv_kernel<<<Tt / 256, 256>>>(u, yobs, D, out);
}

// round 8
// speedup vs baseline: 1.8637x; 1.8637x over previous
#include <cuda_runtime.h>
#include <cuda_fp16.h>
#include <cuda_fp8.h>
#include <math.h>

// StateNeuronSep: Luenberger observer, ORDER=4096, SEQ=4096, IN=8, OUT=1.
//
// y_t = r_t.h0 + sum_{k<t} [ (r_k B').u_{t-1-k} + (r_k L) yobs_{t-1-k} ] + D.u_t
// r_{k+1} = r_k A - (r_k.L) C   (row Krylov, rank-1 fold; M never materialized)
// rho(M) ~ 0.9 => truncate at K=144. Precision ladder on A:
//   k in [0,8):    fp32 A     (64 MB/step)
//   k in [8,64):   fp16 copy  (32 MB/step)
//   k in [64,144): fp8 e4m3 copy, scaled 2^14 (16 MB/step)
// R5-proven structure: QP partial planes, every CTA re-assembles r_k and
// redundantly computes s = r_k.L (deterministic fixed-order reductions).

#define Nn 4096
#define Tt 4096
#define INW 8
#define K_TR 144
#define K_F32 8
#define FP8_START 64
#define QP 4
#define FP8_SCALE_INV 6.103515625e-05f   // 2^-14

// Scratch (device globals; no allocation allowed)
__device__ float   g_R[K_TR][QP][Nn];            // 9.4 MB partial planes
__device__ float   g_PQ[K_TR][12];               // p[0..7], [8]=s_k, [9]=r_k.1
__device__ __half2 g_Ah[(Nn * Nn) / 2];          // 32 MB fp16 A
__device__ unsigned long long g_A8[(Nn * Nn) / 8];  // 16 MB fp8 (e4m3, x2^14) A

// ---------------------------------------------------------------------------
// one-time A (fp32) -> fp16 + scaled fp8.  4M float4 elements.
__global__ void __launch_bounds__(256) convert_kernel(const float4* __restrict__ A4) {
    int idx = blockIdx.x * 256 + threadIdx.x;      // 0 .. 4M-1
    float4 v = A4[idx];
    __half2 h0 = __floats2half2_rn(v.x, v.y);
    __half2 h1 = __floats2half2_rn(v.z, v.w);
    uint2 packed;
    packed.x = *reinterpret_cast<unsigned int*>(&h0);
    packed.y = *reinterpret_cast<unsigned int*>(&h1);
    ((uint2*)g_Ah)[idx] = packed;
    const float sc = 16384.f;                      // max |A|*2^14 ~ 399 < 448
    unsigned int b0 = __nv_cvt_float_to_fp8(v.x * sc, __NV_SATFINITE, __NV_E4M3);
    unsigned int b1 = __nv_cvt_float_to_fp8(v.y * sc, __NV_SATFINITE, __NV_E4M3);
    unsigned int b2 = __nv_cvt_float_to_fp8(v.z * sc, __NV_SATFINITE, __NV_E4M3);
    unsigned int b3 = __nv_cvt_float_to_fp8(v.w * sc, __NV_SATFINITE, __NV_E4M3);
    ((unsigned int*)g_A8)[idx] = b0 | (b1 << 8) | (b2 << 16) | (b3 << 24);
}

// ---------------------------------------------------------------------------
__global__ void init_kernel(const float* __restrict__ C) {
    int j = blockIdx.x * 256 + threadIdx.x;
    if (j < Nn) {
        g_R[0][0][j] = C[j];
        g_R[0][1][j] = 0.f;
        g_R[0][2][j] = 0.f;
        g_R[0][3][j] = 0.f;
    }
}

// ---------------------------------------------------------------------------
// Shared prologue/epilogue pieces (macros keep each kernel self-contained).
#define ASSEMBLE_R()                                                           \
    {                                                                          \
        const float4* p0 = (const float4*)g_R[k][0];                           \
        const float4* p1 = (const float4*)g_R[k][1];                           \
        const float4* p2 = (const float4*)g_R[k][2];                           \
        const float4* p3 = (const float4*)g_R[k][3];                           \
        float4* r4 = (float4*)r_s;                                             \
        _Pragma("unroll")                                                      \
        for (int it = 0; it < 2; it++) {                                       \
            int idx = tid + it * 512;                                          \
            float4 a = p0[idx], b = p1[idx], c = p2[idx], d = p3[idx];         \
            r4[idx] = make_float4(a.x + b.x + c.x + d.x, a.y + b.y + c.y + d.y,\
                                  a.z + b.z + c.z + d.z, a.w + b.w + c.w + d.w);\
        }                                                                      \
    }                                                                          \
    __syncthreads();

#define REDUCE_S()                                                             \
    {                                                                          \
        const float4* L4 = (const float4*)L;                                   \
        const float4* r4c = (const float4*)r_s;                                \
        float4 la = L4[tid * 2], lb = L4[tid * 2 + 1];                         \
        float4 ra = r4c[tid * 2], rb = r4c[tid * 2 + 1];                       \
        float sp = ra.x * la.x + ra.y * la.y + ra.z * la.z + ra.w * la.w       \
                 + rb.x * lb.x + rb.y * lb.y + rb.z * lb.z + rb.w * lb.w;      \
        _Pragma("unroll")                                                      \
        for (int off = 16; off > 0; off >>= 1)                                 \
            sp += __shfl_xor_sync(0xffffffffu, sp, off);                       \
        if (lane == 0) red_s[w] = sp;                                          \
    }                                                                          \
    __syncthreads();                                                           \
    if (tid == 0) {                                                            \
        float ssum = 0.f;                                                      \
        _Pragma("unroll")                                                      \
        for (int q = 0; q < 16; q++) ssum += red_s[q];                         \
        s_sh = ssum;                                                           \
    }                                                                          \
    __syncthreads();                                                           \
    float s = s_sh;

// ---------------------------------------------------------------------------
// fp32 step: grid (64 col-tiles of 64, 4 row-quarters), block 512 (16 warps).
__global__ void __launch_bounds__(512) step32_kernel(int k,
                                                     const float* __restrict__ A,
                                                     const float* __restrict__ C,
                                                     const float* __restrict__ L) {
    __shared__ __align__(16) float r_s[Nn];   // 16 KB
    __shared__ float acc_s[16][64];
    __shared__ float red_s[16];
    __shared__ float s_sh;

    int tid  = threadIdx.x;
    int lane = tid & 31;
    int w    = tid >> 5;

    ASSEMBLE_R()

    int colbase = blockIdx.x * 64;
    size_t c2   = (size_t)(colbase >> 1) + lane;
    int ibase   = blockIdx.y * 1024 + w * 64;

    const unsigned long long* Au = (const unsigned long long*)A;
    unsigned long long acc0 = 0ull, acc1 = 0ull;

    #pragma unroll 4
    for (int ii = 0; ii < 64; ii += 2) {
        int i0 = ibase + ii;
        float r0 = r_s[i0];
        float r1 = r_s[i0 + 1];
        unsigned long long a0 = Au[(size_t)i0 * (Nn / 2) + c2];
        unsigned long long a1 = Au[(size_t)(i0 + 1) * (Nn / 2) + c2];
        unsigned long long rr0, rr1;
        asm("mov.b64 %0, {%1, %1};" : "=l"(rr0) : "r"(__float_as_uint(r0)));
        asm("mov.b64 %0, {%1, %1};" : "=l"(rr1) : "r"(__float_as_uint(r1)));
        asm("fma.rn.f32x2 %0, %1, %2, %3;" : "=l"(acc0) : "l"(a0), "l"(rr0), "l"(acc0));
        asm("fma.rn.f32x2 %0, %1, %2, %3;" : "=l"(acc1) : "l"(a1), "l"(rr1), "l"(acc1));
    }
    unsigned long long accm;
    asm("add.rn.f32x2 %0, %1, %2;" : "=l"(accm) : "l"(acc0), "l"(acc1));
    unsigned int lo_u, hi_u;
    asm("mov.b64 {%0, %1}, %2;" : "=r"(lo_u), "=r"(hi_u) : "l"(accm));
    acc_s[w][lane * 2]     = __uint_as_float(lo_u);
    acc_s[w][lane * 2 + 1] = __uint_as_float(hi_u);

    REDUCE_S()

    if (tid < 64) {
        float t = 0.f;
        #pragma unroll
        for (int q = 0; q < 16; q++) t += acc_s[q][tid];
        int j = colbase + tid;
        if (blockIdx.y == 0) t -= s * C[j];
        g_R[k + 1][blockIdx.y][j] = t;
    }
}

// ---------------------------------------------------------------------------
// fp16 step: grid (32 col-tiles of 128, 4 row-quarters), block 512.
__global__ void __launch_bounds__(512) step16_kernel(int k,
                                                     const float* __restrict__ C,
                                                     const float* __restrict__ L) {
    __shared__ __align__(16) float r_s[Nn];
    __shared__ float acc_s[16][128];
    __shared__ float red_s[16];
    __shared__ float s_sh;

    int tid  = threadIdx.x;
    int lane = tid & 31;
    int w    = tid >> 5;

    ASSEMBLE_R()

    int colbase = blockIdx.x * 128;
    size_t c4   = (size_t)(colbase >> 2) + lane;   // u64 = 4 halves
    int ibase   = blockIdx.y * 1024 + w * 64;

    const unsigned long long* Au = (const unsigned long long*)g_Ah;
    float a0 = 0.f, a1 = 0.f, a2 = 0.f, a3 = 0.f;

    #pragma unroll 4
    for (int ii = 0; ii < 64; ii++) {
        int i = ibase + ii;
        float rv = r_s[i];
        unsigned long long av = Au[(size_t)i * (Nn / 4) + c4];
        unsigned int lo = (unsigned int)av;
        unsigned int hi = (unsigned int)(av >> 32);
        float2 f0 = __half22float2(*(__half2*)&lo);
        float2 f1 = __half22float2(*(__half2*)&hi);
        a0 += rv * f0.x; a1 += rv * f0.y;
        a2 += rv * f1.x; a3 += rv * f1.y;
    }
    acc_s[w][lane * 4]     = a0;
    acc_s[w][lane * 4 + 1] = a1;
    acc_s[w][lane * 4 + 2] = a2;
    acc_s[w][lane * 4 + 3] = a3;

    REDUCE_S()

    if (tid < 128) {
        float t = 0.f;
        #pragma unroll
        for (int q = 0; q < 16; q++) t += acc_s[q][tid];
        int j = colbase + tid;
        if (blockIdx.y == 0) t -= s * C[j];
        g_R[k + 1][blockIdx.y][j] = t;
    }
}

// ---------------------------------------------------------------------------
// fp8 step: grid (32 col-tiles of 128, 4 row-quarters), block 512.
// Lane covers 8 cols (u64 = 8 e4m3); half-warps handle row parity.
__global__ void __launch_bounds__(512) step8_kernel(int k,
                                                    const float* __restrict__ C,
                                                    const float* __restrict__ L) {
    __shared__ __align__(16) float r_s[Nn];
    __shared__ float acc_s[16][128];
    __shared__ float red_s[16];
    __shared__ float s_sh;

    int tid  = threadIdx.x;
    int lane = tid & 31;
    int w    = tid >> 5;

    ASSEMBLE_R()

    int colbase = blockIdx.x * 128;
    int ibase   = blockIdx.y * 1024 + w * 64;
    int half    = lane >> 4;                       // 0/1: row parity
    int lpos    = lane & 15;                       // col-group within tile
    size_t cu   = (size_t)(colbase >> 3) + lpos;   // u64 index within a row

    const unsigned long long* Au = g_A8;           // row = Nn/8 = 512 u64
    float acc[8];
    #pragma unroll
    for (int c = 0; c < 8; c++) acc[c] = 0.f;

    #pragma unroll 4
    for (int ii = 0; ii < 64; ii += 2) {
        int i = ibase + ii + half;
        float rv = r_s[i];
        unsigned long long av = Au[(size_t)i * (Nn / 8) + cu];
        unsigned short p0 = (unsigned short)av;
        unsigned short p1 = (unsigned short)(av >> 16);
        unsigned short p2 = (unsigned short)(av >> 32);
        unsigned short p3 = (unsigned short)(av >> 48);
        unsigned int h01, h23, h45, h67;
        asm("cvt.rn.f16x2.e4m3x2 %0, %1;" : "=r"(h01) : "h"(p0));
        asm("cvt.rn.f16x2.e4m3x2 %0, %1;" : "=r"(h23) : "h"(p1));
        asm("cvt.rn.f16x2.e4m3x2 %0, %1;" : "=r"(h45) : "h"(p2));
        asm("cvt.rn.f16x2.e4m3x2 %0, %1;" : "=r"(h67) : "h"(p3));
        float2 f0 = __half22float2(*(__half2*)&h01);
        float2 f1 = __half22float2(*(__half2*)&h23);
        float2 f2 = __half22float2(*(__half2*)&h45);
        float2 f3 = __half22float2(*(__half2*)&h67);
        acc[0] += rv * f0.x; acc[1] += rv * f0.y;
        acc[2] += rv * f1.x; acc[3] += rv * f1.y;
        acc[4] += rv * f2.x; acc[5] += rv * f2.y;
        acc[6] += rv * f3.x; acc[7] += rv * f3.y;
    }

    // fold the two row-parity half-warps (lanes 0..15 keep the sum)
    #pragma unroll
    for (int c = 0; c < 8; c++)
        acc[c] += __shfl_down_sync(0xffffffffu, acc[c], 16);
    if (lane < 16) {
        #pragma unroll
        for (int c = 0; c < 8; c++)
            acc_s[w][lpos * 8 + c] = acc[c];
    }

    REDUCE_S()

    if (tid < 128) {
        float t = 0.f;
        #pragma unroll
        for (int q = 0; q < 16; q++) t += acc_s[q][tid];
        t *= FP8_SCALE_INV;
        int j = colbase + tid;
        if (blockIdx.y == 0) t -= s * C[j];
        g_R[k + 1][blockIdx.y][j] = t;
    }
}

// ---------------------------------------------------------------------------
// phi: p_k = r_k B - s_k D, q_k = s_k = r_k.L, a_k = r_k.1
__global__ void __launch_bounds__(256) phi_kernel(const float* __restrict__ B,
                                                  const float* __restrict__ D,
                                                  const float* __restrict__ L) {
    __shared__ float r_s[Nn];
    __shared__ float red[256];
    __shared__ float sres[10];
    int k = blockIdx.x;
    int tid = threadIdx.x;

    for (int i = tid; i < Nn; i += 256)
        r_s[i] = g_R[k][0][i] + g_R[k][1][i] + g_R[k][2][i] + g_R[k][3][i];
    __syncthreads();

    float acc[10];
    #pragma unroll
    for (int c = 0; c < 10; c++) acc[c] = 0.f;

    for (int i = tid; i < Nn; i += 256) {
        float rv = r_s[i];
        float4 b0 = *(const float4*)(B + i * INW);
        float4 b1 = *(const float4*)(B + i * INW + 4);
        acc[0] += rv * b0.x; acc[1] += rv * b0.y;
        acc[2] += rv * b0.z; acc[3] += rv * b0.w;
        acc[4] += rv * b1.x; acc[5] += rv * b1.y;
        acc[6] += rv * b1.z; acc[7] += rv * b1.w;
        acc[8] += rv * L[i];
        acc[9] += rv;                 // h0 = ones
    }

    #pragma unroll
    for (int c = 0; c < 10; c++) {
        red[tid] = acc[c];
        __syncthreads();
        for (int off = 128; off > 0; off >>= 1) {
            if (tid < off) red[tid] += red[tid + off];
            __syncthreads();
        }
        if (tid == 0) sres[c] = red[0];
        __syncthreads();
    }

    if (tid == 0) {
        float s = sres[8];
        #pragma unroll
        for (int c = 0; c < INW; c++) g_PQ[k][c] = sres[c] - s * D[c];
        g_PQ[k][8] = s;
        g_PQ[k][9] = sres[9];
    }
}

// ---------------------------------------------------------------------------
// conv: y_t = a_t + D.u_t + sum_{k<min(t,K)} [ p_k.u_{t-1-k} + q_k yobs_{t-1-k} ]
__global__ void __launch_bounds__(256) conv_kernel(const float* __restrict__ u,
                                                   const float* __restrict__ yobs,
                                                   const float* __restrict__ D,
                                                   float* __restrict__ out) {
    __shared__ float pq[K_TR][10];
    __shared__ float us[512][9];      // [local sidx][0..7]=u, [8]=yobs
    int tid = threadIdx.x;
    int t0  = blockIdx.x * 256;

    for (int idx = tid; idx < K_TR * 10; idx += 256)
        pq[idx / 10][idx % 10] = g_PQ[idx / 10][idx % 10];

    for (int l = tid; l < 512; l += 256) {
        int sidx = t0 - 256 + l;
        if (sidx >= 0 && sidx < Tt) {
            #pragma unroll
            for (int c = 0; c < INW; c++) us[l][c] = u[c * Tt + sidx];
            us[l][8] = yobs[sidx];
        } else {
            #pragma unroll
            for (int c = 0; c < 9; c++) us[l][c] = 0.f;
        }
    }
    __syncthreads();

    int t = t0 + tid;
    float y = 0.f;
    #pragma unroll
    for (int c = 0; c < INW; c++) y += D[c] * u[c * Tt + t];
    if (t < K_TR) y += pq[t][9];      // a_t = r_t . h0 (decayed ~0 beyond K)

    int kmax = min(t, K_TR);
    for (int kk = 0; kk < kmax; kk++) {
        int l = tid + 255 - kk;       // (t-1-kk) - (t0-256)
        float a = pq[kk][8] * us[l][8];
        #pragma unroll
        for (int c = 0; c < INW; c++) a += pq[kk][c] * us[l][c];
        y += a;
    }
    out[t] = 3.f * tanhf(y);
}

// ---------------------------------------------------------------------------
extern "C" void kernel_launch(void* const* d_in, const int* in_sizes, int n_in,
                              void* d_out, int out_size) {
    const float* u    = (const float*)d_in[0];  // [8,4096]
    const float* yobs = (const float*)d_in[1];  // [1,4096]
    const float* A    = (const float*)d_in[2];  // [4096,4096]
    const float* B    = (const float*)d_in[3];  // [4096,8]
    const float* C    = (const float*)d_in[4];  // [1,4096]
    const float* D    = (const float*)d_in[5];  // [1,8]
    const float* L    = (const float*)d_in[6];  // [4096,1]
    float* out = (float*)d_out;                 // [1,4096]
    (void)in_sizes; (void)n_in; (void)out_size;

    convert_kernel<<<(Nn * Nn / 4) / 256, 256>>>((const float4*)A);
    init_kernel<<<Nn / 256, 256>>>(C);
    for (int k = 0; k < K_F32; k++)
        step32_kernel<<<dim3(64, QP), 512>>>(k, A, C, L);
    for (int k = K_F32; k < FP8_START; k++)
        step16_kernel<<<dim3(32, QP), 512>>>(k, C, L);
    for (int k = FP8_START; k < K_TR - 1; k++)
        step8_kernel<<<dim3(32, QP), 512>>>(k, C, L);
    phi_kernel<<<K_TR, 256>>>(B, D, L);
    conv_kernel<<<Tt / 256, 256>>>(u, yobs, D, out);
}

// round 9
// speedup vs baseline: 1.9332x; 1.0373x over previous
#include <cuda_runtime.h>
#include <cuda_fp16.h>
#include <cuda_fp8.h>
#include <math.h>

// StateNeuronSep: Luenberger observer, ORDER=4096, SEQ=4096, IN=8, OUT=1.
//
// y_t = r_t.h0 + sum_{k<t} [ (r_k B').u_{t-1-k} + (r_k L) yobs_{t-1-k} ] + D.u_t
// r_{k+1} = r_k A - (r_k.L) C   (row Krylov, rank-1 fold; M never materialized)
// Precision ladder on A:  k in [0,8) fp32 | [8,48) fp16 | [48,128) fp8 e4m3 x2^14.
// Each CTA assembles only its own 1024-row slice of r_k (4 planes x 1024).
// s = r_k.L is carried as per-CTA partial dots (g_S), summed consumer-side in
// fixed index order => deterministic, no atomics, no serial tail CTA.

#define Nn 4096
#define Tt 4096
#define INW 8
#define K_TR 128
#define K_F32 8
#define FP8_START 48
#define QP 4
#define FP8_SCALE_INV 6.103515625e-05f   // 2^-14

// Scratch (device globals; no allocation allowed)
__device__ float   g_R[K_TR][QP][Nn];            // partial planes
__device__ float   g_S[K_TR][256];               // per-CTA partial s = r.L
__device__ float   g_PQ[K_TR][12];               // p[0..7], [8]=s_k, [9]=r_k.1
__device__ __half2 g_Ah[(Nn * Nn) / 2];          // 32 MB fp16 A
__device__ unsigned long long g_A8[(Nn * Nn) / 8];  // 16 MB fp8 (e4m3, x2^14) A

// ---------------------------------------------------------------------------
// one-time A (fp32) -> fp16 + scaled fp8.  4M float4 elements.
__global__ void __launch_bounds__(256) convert_kernel(const float4* __restrict__ A4) {
    int idx = blockIdx.x * 256 + threadIdx.x;      // 0 .. 4M-1
    float4 v = A4[idx];
    __half2 h0 = __floats2half2_rn(v.x, v.y);
    __half2 h1 = __floats2half2_rn(v.z, v.w);
    uint2 packed;
    packed.x = *reinterpret_cast<unsigned int*>(&h0);
    packed.y = *reinterpret_cast<unsigned int*>(&h1);
    ((uint2*)g_Ah)[idx] = packed;
    const float sc = 16384.f;                      // max |A|*2^14 ~ 399 < 448
    unsigned int b0 = __nv_cvt_float_to_fp8(v.x * sc, __NV_SATFINITE, __NV_E4M3);
    unsigned int b1 = __nv_cvt_float_to_fp8(v.y * sc, __NV_SATFINITE, __NV_E4M3);
    unsigned int b2 = __nv_cvt_float_to_fp8(v.z * sc, __NV_SATFINITE, __NV_E4M3);
    unsigned int b3 = __nv_cvt_float_to_fp8(v.w * sc, __NV_SATFINITE, __NV_E4M3);
    ((unsigned int*)g_A8)[idx] = b0 | (b1 << 8) | (b2 << 16) | (b3 << 24);
}

// ---------------------------------------------------------------------------
// init: r_0 = C in plane 0, zeros elsewhere; block 0 computes s_0 = C.L.
__global__ void init_kernel(const float* __restrict__ C,
                            const float* __restrict__ L) {
    __shared__ float red[256];
    int tid = threadIdx.x;
    int j = blockIdx.x * 256 + tid;
    if (j < Nn) {
        g_R[0][0][j] = C[j];
        g_R[0][1][j] = 0.f;
        g_R[0][2][j] = 0.f;
        g_R[0][3][j] = 0.f;
    }
    if (blockIdx.x == 0) {
        float sp = 0.f;
        for (int i = tid; i < Nn; i += 256) sp += C[i] * L[i];
        red[tid] = sp;
        __syncthreads();
        for (int off = 128; off > 0; off >>= 1) {
            if (tid < off) red[tid] += red[tid + off];
            __syncthreads();
        }
        if (tid == 0) g_S[0][0] = red[0];
    }
}

// ---------------------------------------------------------------------------
// Shared prologue: slice-assemble r_k (own row quarter, 1024 floats) and
// read s_k from the previous step's cnt partials (fixed order => deterministic).
#define PROLOGUE()                                                             \
    {                                                                          \
        if (tid < 256) {                                                       \
            const float4* p0 = (const float4*)&g_R[k][0][blockIdx.y * 1024];   \
            const float4* p1 = (const float4*)&g_R[k][1][blockIdx.y * 1024];   \
            const float4* p2 = (const float4*)&g_R[k][2][blockIdx.y * 1024];   \
            const float4* p3 = (const float4*)&g_R[k][3][blockIdx.y * 1024];   \
            float4 a = p0[tid], b = p1[tid], c = p2[tid], d = p3[tid];         \
            ((float4*)r_s)[tid] =                                              \
                make_float4(a.x + b.x + c.x + d.x, a.y + b.y + c.y + d.y,      \
                            a.z + b.z + c.z + d.z, a.w + b.w + c.w + d.w);     \
        } else if (tid >= 480) {                                               \
            int l2 = tid - 480;   /* one warp sums the s partials */           \
            float sp = 0.f;                                                    \
            for (int idx = l2; idx < cnt; idx += 32) sp += g_S[k][idx];        \
            _Pragma("unroll")                                                  \
            for (int off = 16; off > 0; off >>= 1)                             \
                sp += __shfl_xor_sync(0xffffffffu, sp, off);                   \
            if (l2 == 0) s_sh = sp;                                            \
        }                                                                      \
    }                                                                          \
    __syncthreads();

// Shared epilogue: reduce warp partials per column, fold -s*C on plane 0,
// write plane + per-CTA partial dot with L.
#define EPILOGUE(WIDTH, SCALE_EXPR)                                            \
    if (tid < (WIDTH)) {                                                       \
        float t = 0.f;                                                         \
        _Pragma("unroll")                                                      \
        for (int q = 0; q < 16; q++) t += acc_s[q][tid];                       \
        t = (SCALE_EXPR);                                                      \
        int j = colbase + tid;                                                 \
        if (blockIdx.y == 0) t -= s_sh * C[j];                                 \
        g_R[k + 1][blockIdx.y][j] = t;                                         \
        dot_s[tid] = t * L[j];                                                 \
    }                                                                          \
    __syncthreads();                                                           \
    for (int off = (WIDTH) / 2; off > 0; off >>= 1) {                          \
        if (tid < off) dot_s[tid] += dot_s[tid + off];                         \
        __syncthreads();                                                       \
    }                                                                          \
    if (tid == 0)                                                              \
        g_S[k + 1][blockIdx.y * gridDim.x + blockIdx.x] = dot_s[0];

// ---------------------------------------------------------------------------
// fp32 step: grid (64 col-tiles of 64, 4 row-quarters), block 512 (16 warps).
__global__ void __launch_bounds__(512) step32_kernel(int k, int cnt,
                                                     const float* __restrict__ A,
                                                     const float* __restrict__ C,
                                                     const float* __restrict__ L) {
    __shared__ __align__(16) float r_s[1024];   // own row-quarter slice
    __shared__ float acc_s[16][64];
    __shared__ float dot_s[64];
    __shared__ float s_sh;

    int tid  = threadIdx.x;
    int lane = tid & 31;
    int w    = tid >> 5;

    PROLOGUE()

    int colbase = blockIdx.x * 64;
    size_t c2   = (size_t)(colbase >> 1) + lane;
    int rowg    = blockIdx.y * 1024 + w * 64;   // global base row for this warp
    int il      = w * 64;                        // local base row in r_s

    const unsigned long long* Au = (const unsigned long long*)A;
    unsigned long long acc0 = 0ull, acc1 = 0ull;

    #pragma unroll 4
    for (int ii = 0; ii < 64; ii += 2) {
        float r0 = r_s[il + ii];
        float r1 = r_s[il + ii + 1];
        size_t gi = (size_t)(rowg + ii);
        unsigned long long a0 = Au[gi * (Nn / 2) + c2];
        unsigned long long a1 = Au[(gi + 1) * (Nn / 2) + c2];
        unsigned long long rr0, rr1;
        asm("mov.b64 %0, {%1, %1};" : "=l"(rr0) : "r"(__float_as_uint(r0)));
        asm("mov.b64 %0, {%1, %1};" : "=l"(rr1) : "r"(__float_as_uint(r1)));
        asm("fma.rn.f32x2 %0, %1, %2, %3;" : "=l"(acc0) : "l"(a0), "l"(rr0), "l"(acc0));
        asm("fma.rn.f32x2 %0, %1, %2, %3;" : "=l"(acc1) : "l"(a1), "l"(rr1), "l"(acc1));
    }
    unsigned long long accm;
    asm("add.rn.f32x2 %0, %1, %2;" : "=l"(accm) : "l"(acc0), "l"(acc1));
    unsigned int lo_u, hi_u;
    asm("mov.b64 {%0, %1}, %2;" : "=r"(lo_u), "=r"(hi_u) : "l"(accm));
    acc_s[w][lane * 2]     = __uint_as_float(lo_u);
    acc_s[w][lane * 2 + 1] = __uint_as_float(hi_u);
    __syncthreads();

    EPILOGUE(64, t)
}

// ---------------------------------------------------------------------------
// fp16 step: grid (32 col-tiles of 128, 4 row-quarters), block 512.
__global__ void __launch_bounds__(512) step16_kernel(int k, int cnt,
                                                     const float* __restrict__ C,
                                                     const float* __restrict__ L) {
    __shared__ __align__(16) float r_s[1024];
    __shared__ float acc_s[16][128];
    __shared__ float dot_s[128];
    __shared__ float s_sh;

    int tid  = threadIdx.x;
    int lane = tid & 31;
    int w    = tid >> 5;

    PROLOGUE()

    int colbase = blockIdx.x * 128;
    size_t c4   = (size_t)(colbase >> 2) + lane;   // u64 = 4 halves
    int rowg    = blockIdx.y * 1024 + w * 64;
    int il      = w * 64;

    const unsigned long long* Au = (const unsigned long long*)g_Ah;
    float a0 = 0.f, a1 = 0.f, a2 = 0.f, a3 = 0.f;

    #pragma unroll 4
    for (int ii = 0; ii < 64; ii++) {
        float rv = r_s[il + ii];
        unsigned long long av = Au[(size_t)(rowg + ii) * (Nn / 4) + c4];
        unsigned int lo = (unsigned int)av;
        unsigned int hi = (unsigned int)(av >> 32);
        float2 f0 = __half22float2(*(__half2*)&lo);
        float2 f1 = __half22float2(*(__half2*)&hi);
        a0 += rv * f0.x; a1 += rv * f0.y;
        a2 += rv * f1.x; a3 += rv * f1.y;
    }
    acc_s[w][lane * 4]     = a0;
    acc_s[w][lane * 4 + 1] = a1;
    acc_s[w][lane * 4 + 2] = a2;
    acc_s[w][lane * 4 + 3] = a3;
    __syncthreads();

    EPILOGUE(128, t)
}

// ---------------------------------------------------------------------------
// fp8 step: grid (32 col-tiles of 128, 4 row-quarters), block 512.
// Lane covers 8 cols (u64 = 8 e4m3); half-warps handle row parity.
__global__ void __launch_bounds__(512) step8_kernel(int k, int cnt,
                                                    const float* __restrict__ C,
                                                    const float* __restrict__ L) {
    __shared__ __align__(16) float r_s[1024];
    __shared__ float acc_s[16][128];
    __shared__ float dot_s[128];
    __shared__ float s_sh;

    int tid  = threadIdx.x;
    int lane = tid & 31;
    int w    = tid >> 5;

    PROLOGUE()

    int colbase = blockIdx.x * 128;
    int rowg    = blockIdx.y * 1024 + w * 64;
    int il      = w * 64;
    int half    = lane >> 4;                       // 0/1: row parity
    int lpos    = lane & 15;                       // col-group within tile
    size_t cu   = (size_t)(colbase >> 3) + lpos;   // u64 index within a row

    const unsigned long long* Au = g_A8;           // row = Nn/8 = 512 u64
    float acc[8];
    #pragma unroll
    for (int c = 0; c < 8; c++) acc[c] = 0.f;

    #pragma unroll 4
    for (int ii = 0; ii < 64; ii += 2) {
        float rv = r_s[il + ii + half];
        unsigned long long av = Au[(size_t)(rowg + ii + half) * (Nn / 8) + cu];
        unsigned short p0 = (unsigned short)av;
        unsigned short p1 = (unsigned short)(av >> 16);
        unsigned short p2 = (unsigned short)(av >> 32);
        unsigned short p3 = (unsigned short)(av >> 48);
        unsigned int h01, h23, h45, h67;
        asm("cvt.rn.f16x2.e4m3x2 %0, %1;" : "=r"(h01) : "h"(p0));
        asm("cvt.rn.f16x2.e4m3x2 %0, %1;" : "=r"(h23) : "h"(p1));
        asm("cvt.rn.f16x2.e4m3x2 %0, %1;" : "=r"(h45) : "h"(p2));
        asm("cvt.rn.f16x2.e4m3x2 %0, %1;" : "=r"(h67) : "h"(p3));
        float2 f0 = __half22float2(*(__half2*)&h01);
        float2 f1 = __half22float2(*(__half2*)&h23);
        float2 f2 = __half22float2(*(__half2*)&h45);
        float2 f3 = __half22float2(*(__half2*)&h67);
        acc[0] += rv * f0.x; acc[1] += rv * f0.y;
        acc[2] += rv * f1.x; acc[3] += rv * f1.y;
        acc[4] += rv * f2.x; acc[5] += rv * f2.y;
        acc[6] += rv * f3.x; acc[7] += rv * f3.y;
    }

    // fold the two row-parity half-warps (lanes 0..15 keep the sum)
    #pragma unroll
    for (int c = 0; c < 8; c++)
        acc[c] += __shfl_down_sync(0xffffffffu, acc[c], 16);
    if (lane < 16) {
        #pragma unroll
        for (int c = 0; c < 8; c++)
            acc_s[w][lpos * 8 + c] = acc[c];
    }
    __syncthreads();

    EPILOGUE(128, t * FP8_SCALE_INV)
}

// ---------------------------------------------------------------------------
// phi: p_k = r_k B - s_k D, q_k = s_k = r_k.L, a_k = r_k.1
__global__ void __launch_bounds__(256) phi_kernel(const float* __restrict__ B,
                                                  const float* __restrict__ D,
                                                  const float* __restrict__ L) {
    __shared__ float r_s[Nn];
    __shared__ float red[256];
    __shared__ float sres[10];
    int k = blockIdx.x;
    int tid = threadIdx.x;

    for (int i = tid; i < Nn; i += 256)
        r_s[i] = g_R[k][0][i] + g_R[k][1][i] + g_R[k][2][i] + g_R[k][3][i];
    __syncthreads();

    float acc[10];
    #pragma unroll
    for (int c = 0; c < 10; c++) acc[c] = 0.f;

    for (int i = tid; i < Nn; i += 256) {
        float rv = r_s[i];
        float4 b0 = *(const float4*)(B + i * INW);
        float4 b1 = *(const float4*)(B + i * INW + 4);
        acc[0] += rv * b0.x; acc[1] += rv * b0.y;
        acc[2] += rv * b0.z; acc[3] += rv * b0.w;
        acc[4] += rv * b1.x; acc[5] += rv * b1.y;
        acc[6] += rv * b1.z; acc[7] += rv * b1.w;
        acc[8] += rv * L[i];
        acc[9] += rv;                 // h0 = ones
    }

    #pragma unroll
    for (int c = 0; c < 10; c++) {
        red[tid] = acc[c];
        __syncthreads();
        for (int off = 128; off > 0; off >>= 1) {
            if (tid < off) red[tid] += red[tid + off];
            __syncthreads();
        }
        if (tid == 0) sres[c] = red[0];
        __syncthreads();
    }

    if (tid == 0) {
        float s = sres[8];
        #pragma unroll
        for (int c = 0; c < INW; c++) g_PQ[k][c] = sres[c] - s * D[c];
        g_PQ[k][8] = s;
        g_PQ[k][9] = sres[9];
    }
}

// ---------------------------------------------------------------------------
// conv: y_t = a_t + D.u_t + sum_{k<min(t,K)} [ p_k.u_{t-1-k} + q_k yobs_{t-1-k} ]
__global__ void __launch_bounds__(256) conv_kernel(const float* __restrict__ u,
                                                   const float* __restrict__ yobs,
                                                   const float* __restrict__ D,
                                                   float* __restrict__ out) {
    __shared__ float pq[K_TR][10];
    __shared__ float us[512][9];      // [local sidx][0..7]=u, [8]=yobs
    int tid = threadIdx.x;
    int t0  = blockIdx.x * 256;

    for (int idx = tid; idx < K_TR * 10; idx += 256)
        pq[idx / 10][idx % 10] = g_PQ[idx / 10][idx % 10];

    for (int l = tid; l < 512; l += 256) {
        int sidx = t0 - 256 + l;
        if (sidx >= 0 && sidx < Tt) {
            #pragma unroll
            for (int c = 0; c < INW; c++) us[l][c] = u[c * Tt + sidx];
            us[l][8] = yobs[sidx];
        } else {
            #pragma unroll
            for (int c = 0; c < 9; c++) us[l][c] = 0.f;
        }
    }
    __syncthreads();

    int t = t0 + tid;
    float y = 0.f;
    #pragma unroll
    for (int c = 0; c < INW; c++) y += D[c] * u[c * Tt + t];
    if (t < K_TR) y += pq[t][9];      // a_t = r_t . h0 (decayed ~0 beyond K)

    int kmax = min(t, K_TR);
    for (int kk = 0; kk < kmax; kk++) {
        int l = tid + 255 - kk;       // (t-1-kk) - (t0-256)
        float a = pq[kk][8] * us[l][8];
        #pragma unroll
        for (int c = 0; c < INW; c++) a += pq[kk][c] * us[l][c];
        y += a;
    }
    out[t] = 3.f * tanhf(y);
}

// ---------------------------------------------------------------------------
extern "C" void kernel_launch(void* const* d_in, const int* in_sizes, int n_in,
                              void* d_out, int out_size) {
    const float* u    = (const float*)d_in[0];  // [8,4096]
    const float* yobs = (const float*)d_in[1];  // [1,4096]
    const float* A    = (const float*)d_in[2];  // [4096,4096]
    const float* B    = (const float*)d_in[3];  // [4096,8]
    const float* C    = (const float*)d_in[4];  // [1,4096]
    const float* D    = (const float*)d_in[5];  // [1,8]
    const float* L    = (const float*)d_in[6];  // [4096,1]
    float* out = (float*)d_out;                 // [1,4096]
    (void)in_sizes; (void)n_in; (void)out_size;

    convert_kernel<<<(Nn * Nn / 4) / 256, 256>>>((const float4*)A);
    init_kernel<<<Nn / 256, 256>>>(C, L);
    // cnt = number of s-partials produced by the PREVIOUS step
    step32_kernel<<<dim3(64, QP), 512>>>(0, 1, A, C, L);
    for (int k = 1; k < K_F32; k++)
        step32_kernel<<<dim3(64, QP), 512>>>(k, 256, A, C, L);
    step16_kernel<<<dim3(32, QP), 512>>>(K_F32, 256, C, L);
    for (int k = K_F32 + 1; k < FP8_START; k++)
        step16_kernel<<<dim3(32, QP), 512>>>(k, 128, C, L);
    for (int k = FP8_START; k < K_TR - 1; k++)
        step8_kernel<<<dim3(32, QP), 512>>>(k, 128, C, L);
    phi_kernel<<<K_TR, 256>>>(B, D, L);
    conv_kernel<<<Tt / 256, 256>>>(u, yobs, D, out);
}